// round 6
// baseline (speedup 1.0000x reference)
#include <cuda_runtime.h>
#include <cuda_bf16.h>
#include <cstdint>

// B=16, T=2048, C=512, H=256, NO=5, R=8

// ---------------- device scratch ----------------
__device__ float g_musig0[32768 * 5 * 2];
__device__ float g_musig1[32768 * 5 * 2];
__device__ float g_smpart[16 * 5 * 16 * 2];
__device__ float g_gauss[16 * 5 * 17];
__device__ __nv_bfloat16 g_xh[16777216];
__device__ __nv_bfloat16 g_xl[16777216];
__device__ __nv_bfloat16 g_wh[655360];   // transposed: [head][d][k]
__device__ __nv_bfloat16 g_wl[655360];

// ---------------- threefry2x32 (JAX-compatible) ----------------
__host__ __device__ __forceinline__ uint32_t rotl32(uint32_t x, uint32_t r) {
    return (x << r) | (x >> (32u - r));
}
__host__ __device__ __forceinline__ void threefry2x32(
    uint32_t k0, uint32_t k1, uint32_t x0, uint32_t x1,
    uint32_t& o0, uint32_t& o1)
{
    uint32_t k2 = k0 ^ k1 ^ 0x1BD11BDAu;
    x0 += k0; x1 += k1;
#define TF_R(r) { x0 += x1; x1 = rotl32(x1, r); x1 ^= x0; }
    TF_R(13) TF_R(15) TF_R(26) TF_R(6)   x0 += k1; x1 += k2 + 1u;
    TF_R(17) TF_R(29) TF_R(16) TF_R(24)  x0 += k2; x1 += k0 + 2u;
    TF_R(13) TF_R(15) TF_R(26) TF_R(6)   x0 += k0; x1 += k1 + 3u;
    TF_R(17) TF_R(29) TF_R(16) TF_R(24)  x0 += k1; x1 += k2 + 4u;
    TF_R(13) TF_R(15) TF_R(26) TF_R(6)   x0 += k2; x1 += k0 + 5u;
#undef TF_R
    o0 = x0; o1 = x1;
}

__device__ __forceinline__ float bits_to_normal(uint32_t bits) {
    float f = __uint_as_float((bits >> 9) | 0x3f800000u) - 1.0f;
    const float LO = -0.99999994f;
    float u = fmaf(f, 2.0f, LO);
    u = fmaxf(LO, u);
    return 1.41421356237f * erfinvf(u);
}

__device__ __forceinline__ float gelu_exact(float v) {
    return 0.5f * v * (1.0f + erff(v * 0.70710678118654752f));
}

// ---------------- PTX helpers ----------------
__device__ __forceinline__ void cp_async16(uint32_t dst, const void* src) {
    asm volatile("cp.async.cg.shared.global [%0], [%1], 16;\n" :: "r"(dst), "l"(src));
}
__device__ __forceinline__ void ldm_x4(uint32_t& r0, uint32_t& r1, uint32_t& r2, uint32_t& r3, uint32_t addr) {
    asm volatile("ldmatrix.sync.aligned.m8n8.x4.shared.b16 {%0,%1,%2,%3}, [%4];\n"
        : "=r"(r0), "=r"(r1), "=r"(r2), "=r"(r3) : "r"(addr));
}
__device__ __forceinline__ void mma16816(float* c, const uint32_t* a, uint32_t b0, uint32_t b1) {
    asm volatile(
        "mma.sync.aligned.m16n8k16.row.col.f32.bf16.bf16.f32 "
        "{%0,%1,%2,%3},{%4,%5,%6,%7},{%8,%9},{%0,%1,%2,%3};\n"
        : "+f"(c[0]), "+f"(c[1]), "+f"(c[2]), "+f"(c[3])
        : "r"(a[0]), "r"(a[1]), "r"(a[2]), "r"(a[3]), "r"(b0), "r"(b1));
}

// ---------------- Phase 0: precision-split conversions ----------------
__global__ __launch_bounds__(256) void convert_x(const float* __restrict__ x) {
    int i = (blockIdx.x * 256 + threadIdx.x) * 4;
    float4 v = *(const float4*)(x + i);
    __nv_bfloat16 h0 = __float2bfloat16_rn(v.x), h1 = __float2bfloat16_rn(v.y);
    __nv_bfloat16 h2 = __float2bfloat16_rn(v.z), h3 = __float2bfloat16_rn(v.w);
    __nv_bfloat16 l0 = __float2bfloat16_rn(v.x - __bfloat162float(h0));
    __nv_bfloat16 l1 = __float2bfloat16_rn(v.y - __bfloat162float(h1));
    __nv_bfloat16 l2 = __float2bfloat16_rn(v.z - __bfloat162float(h2));
    __nv_bfloat16 l3 = __float2bfloat16_rn(v.w - __bfloat162float(h3));
    *(__nv_bfloat162*)(g_xh + i)     = __nv_bfloat162(h0, h1);
    *(__nv_bfloat162*)(g_xh + i + 2) = __nv_bfloat162(h2, h3);
    *(__nv_bfloat162*)(g_xl + i)     = __nv_bfloat162(l0, l1);
    *(__nv_bfloat162*)(g_xl + i + 2) = __nv_bfloat162(l2, l3);
}

__global__ __launch_bounds__(256) void convert_w(const float* __restrict__ w1) {
    int idx = blockIdx.x * 256 + threadIdx.x;    // 655360 total
    if (idx >= 655360) return;
    int head = idx / (512 * 256);
    int r = idx % (512 * 256);
    int k = r / 256, d = r % 256;
    float v = w1[idx];
    __nv_bfloat16 h = __float2bfloat16_rn(v);
    __nv_bfloat16 l = __float2bfloat16_rn(v - __bfloat162float(h));
    int o = head * 131072 + d * 512 + k;
    g_wh[o] = h;
    g_wl[o] = l;
}

// ---------------- Phase 1: bf16 split tensor-core GEMM + fused epilogue ----------------
__global__ __launch_bounds__(256) void gemm_mma_kernel(
    const float* __restrict__ b1, const float* __restrict__ w2,
    const float* __restrict__ ws)
{
    __shared__ __nv_bfloat16 As[2][128 * 40];
    __shared__ __nv_bfloat16 Bs[2][128 * 40];
    __shared__ float cb1[128], cw20[128], cw21[128], cwsv[128];
    __shared__ float red[2][128][3];
    __shared__ float swred[4];

    int tid = threadIdx.x;
    int lane = tid & 31, warp = tid >> 5;
    int warpM = warp >> 1, warpN = warp & 1;
    int bx = blockIdx.x;
    int head = blockIdx.y >> 1;
    int dtile = blockIdx.y & 1;
    int d0 = dtile * 128;

    uint32_t AsBase = (uint32_t)__cvta_generic_to_shared(&As[0][0]);
    uint32_t BsBase = (uint32_t)__cvta_generic_to_shared(&Bs[0][0]);

    if (tid < 128) {
        int d = d0 + tid;
        cb1[tid]  = b1[head * 256 + d];
        cw20[tid] = w2[d * 2 + 0];
        cw21[tid] = w2[d * 2 + 1];
        cwsv[tid] = ws[d];
    }

    int crow = tid >> 2, cc8 = (tid & 3) * 8;

    auto issue = [&](int s, int buf) {
        int term = s >> 4;
        int k0 = (s & 15) * 32;
        const __nv_bfloat16* Asrc = (term == 2) ? g_xl : g_xh;
        const __nv_bfloat16* Bsrc = (term == 1) ? g_wl : g_wh;
#pragma unroll
        for (int it = 0; it < 2; it++) {
            int row = crow + it * 64;
            cp_async16(AsBase + buf * 10240u + (uint32_t)(row * 40 + cc8) * 2u,
                       Asrc + (size_t)(bx * 128 + row) * 512 + k0 + cc8);
            cp_async16(BsBase + buf * 10240u + (uint32_t)(row * 40 + cc8) * 2u,
                       Bsrc + (size_t)head * 131072 + (size_t)(d0 + row) * 512 + k0 + cc8);
        }
        asm volatile("cp.async.commit_group;\n");
    };

    float acc[2][8][4];
#pragma unroll
    for (int mt = 0; mt < 2; mt++)
#pragma unroll
        for (int nf = 0; nf < 8; nf++)
#pragma unroll
            for (int r = 0; r < 4; r++) acc[mt][nf][r] = 0.f;

    int lr = lane & 15, lc = (lane >> 4) * 8;

    issue(0, 0);
    __syncthreads();

    for (int s = 0; s < 48; s++) {
        int buf = s & 1;
        if (s < 47) issue(s + 1, buf ^ 1);
        if (s < 47) { asm volatile("cp.async.wait_group 1;\n"); }
        else        { asm volatile("cp.async.wait_group 0;\n"); }
        __syncthreads();

#pragma unroll
        for (int kstep = 0; kstep < 2; kstep++) {
            int k0 = kstep * 16;
            uint32_t a[2][4], bf[4][4];
#pragma unroll
            for (int mt = 0; mt < 2; mt++) {
                uint32_t addr = AsBase + buf * 10240u +
                    (uint32_t)((warpM * 32 + mt * 16 + lr) * 40 + k0 + lc) * 2u;
                ldm_x4(a[mt][0], a[mt][1], a[mt][2], a[mt][3], addr);
            }
#pragma unroll
            for (int g = 0; g < 4; g++) {
                uint32_t addr = BsBase + buf * 10240u +
                    (uint32_t)((warpN * 64 + g * 16 + lr) * 40 + k0 + lc) * 2u;
                ldm_x4(bf[g][0], bf[g][1], bf[g][2], bf[g][3], addr);
            }
#pragma unroll
            for (int mt = 0; mt < 2; mt++)
#pragma unroll
                for (int g = 0; g < 4; g++) {
                    mma16816(acc[mt][g * 2 + 0], a[mt], bf[g][0], bf[g][2]);
                    mma16816(acc[mt][g * 2 + 1], a[mt], bf[g][1], bf[g][3]);
                }
        }
        __syncthreads();
    }

#pragma unroll
    for (int mt = 0; mt < 2; mt++) {
#pragma unroll
        for (int r2 = 0; r2 < 2; r2++) {
            float pm = 0.f, ps = 0.f, pw = 0.f;
#pragma unroll
            for (int nf = 0; nf < 8; nf++) {
#pragma unroll
                for (int c01 = 0; c01 < 2; c01++) {
                    int col = warpN * 64 + nf * 8 + (lane & 3) * 2 + c01;
                    float h = gelu_exact(acc[mt][nf][r2 * 2 + c01] + cb1[col]);
                    pm = fmaf(h, cw20[col], pm);
                    ps = fmaf(h, cw21[col], ps);
                    pw = fmaf(h, cwsv[col], pw);
                }
            }
            pm += __shfl_xor_sync(0xffffffffu, pm, 1);
            pm += __shfl_xor_sync(0xffffffffu, pm, 2);
            ps += __shfl_xor_sync(0xffffffffu, ps, 1);
            ps += __shfl_xor_sync(0xffffffffu, ps, 2);
            pw += __shfl_xor_sync(0xffffffffu, pw, 1);
            pw += __shfl_xor_sync(0xffffffffu, pw, 2);
            if ((lane & 3) == 0) {
                int row = warpM * 32 + mt * 16 + (lane >> 2) + r2 * 8;
                red[warpN][row][0] = pm;
                red[warpN][row][1] = ps;
                red[warpN][row][2] = pw;
            }
        }
    }
    __syncthreads();

    if (tid < 128) {
        int row = tid;
        int m = bx * 128 + row;
        float mu  = red[0][row][0] + red[1][row][0];
        float sig = red[0][row][1] + red[1][row][1];
        float wv  = red[0][row][2] + red[1][row][2];
        float* dst = dtile ? g_musig1 : g_musig0;
        dst[((size_t)m * 5 + head) * 2 + 0] = mu;
        dst[((size_t)m * 5 + head) * 2 + 1] = sig;
#pragma unroll
        for (int off = 16; off >= 1; off >>= 1)
            wv += __shfl_xor_sync(0xffffffffu, wv, off);
        if ((tid & 31) == 0) swred[tid >> 5] = wv;
    }
    __syncthreads();
    if (tid == 0) {
        float s = swred[0] + swred[1] + swred[2] + swred[3];
        int b = bx >> 4, mblk = bx & 15;
        g_smpart[((b * 5 + head) * 16 + mblk) * 2 + dtile] = s;
    }
}

// ---------------- Phase 2a: combine d-tile partials + b2 ----------------
__global__ void combine_kernel(const float* __restrict__ b2) {
    int i = blockIdx.x * 256 + threadIdx.x;
    if (i >= 32768 * 5) return;
    float2* p0 = (float2*)g_musig0;
    float2* p1 = (float2*)g_musig1;
    float2 a = p0[i], c = p1[i];
    p0[i] = make_float2(a.x + c.x + b2[0], a.y + c.y + b2[1]);
}

// ---------------- Phase 2b: smooths -> normalized gaussian kernels ----------------
__global__ void reduce_gauss_kernel(const float* __restrict__ bs) {
    int id = threadIdx.x;
    if (id >= 80) return;
    float s = 0.f;
#pragma unroll
    for (int j = 0; j < 32; j++) s += g_smpart[id * 32 + j];
    float sig = s * (1.0f / 2048.0f) + bs[0];
    float denom = sig * sig + 1e-6f;
    float kv[17];
    float ksum = 0.f;
#pragma unroll
    for (int d = 0; d < 17; d++) {
        float t = (float)(d - 8);
        kv[d] = expf(-0.5f * t * t / denom);
        ksum += kv[d];
    }
    float inv = 1.0f / ksum;
#pragma unroll
    for (int d = 0; d < 17; d++) g_gauss[id * 17 + d] = kv[d] * inv;
}

// ---------------- Phase 3a: persistent-T ring noise kernel (SW=32) ----------------
// One block = (b, 32-wide s-slab), full T. 144-row smem ring; per chunk: copy 16-row
// tail to head, generate 128 NEW rows (zero halo recompute), then 17-tap conv with
// 8 outputs/thread from a 24-float register window. 2 blocks/SM for pipe overlap.
__global__ __launch_bounds__(512, 2) void noise_ring_kernel(
    float* __restrict__ out, int head, int S2, int s2log,
    uint32_t key0, uint32_t key1)
{
    constexpr int SW = 32;
    constexpr int TT = 128;          // rows per chunk
    constexpr int W  = TT + 16;      // 144-row ring
    __shared__ float ring[W * SW];   // 18432 B

    int tid  = threadIdx.x;
    int lane = tid & 31;
    int warp = tid >> 5;             // 0..15
    int s0   = blockIdx.x * SW;
    int b    = blockIdx.y;

    float kv[17];
#pragma unroll
    for (int d = 0; d < 17; d++)
        kv[d] = g_gauss[(b * 5 + head) * 17 + d];

    const float2* ms = (const float2*)g_musig0;
    int mbase = b * 2048;
    uint32_t sidx = (uint32_t)(s0 + lane);

    // ---- chunk 0: fill all 144 rows (t = -8 .. 135) ----
#pragma unroll
    for (int it = 0; it < 9; it++) {
        int rr = it * 16 + warp;                 // ring row 0..143
        int t  = rr - 8;
        int tr = (t < 0) ? -t : t;               // reflect (t<=135 here)
        int m  = mbase + tr;
        float2 p = ms[m * 5 + head];
        uint32_t e = ((uint32_t)m << s2log) + sidx;
        uint32_t o0, o1;
        threefry2x32(key0, key1, 0u, e, o0, o1);
        ring[rr * SW + lane] = fmaf(p.y, bits_to_normal(o0 ^ o1), p.x);
    }
    __syncthreads();

    for (int chunk = 0; chunk < 16; chunk++) {
        int t0 = chunk * TT;

        // ---- conv: 128 out rows x 32 cols; warp -> 8 rows, 8 outputs/thread ----
        {
            int k0 = warp * 8;                   // output rows k0..k0+7
            float w[24];
#pragma unroll
            for (int j = 0; j < 24; j++)
                w[j] = ring[(k0 + j) * SW + lane];

            size_t ob = ((size_t)(mbase + t0 + k0) << s2log) + (size_t)(s0 + lane);
#pragma unroll
            for (int o = 0; o < 8; o++) {
                float a = 0.f;
#pragma unroll
                for (int d = 0; d < 17; d++)
                    a = fmaf(kv[d], w[o + d], a);
                __stcs(out + ob + ((size_t)o << s2log), a);
            }
        }
        if (chunk == 15) break;
        __syncthreads();

        // ---- shift: rows 128..143 -> 0..15 (512 elems, 1/thread) ----
        ring[(tid >> 5) * SW + (tid & 31)] = ring[((tid >> 5) + TT) * SW + (tid & 31)];
        __syncthreads();

        // ---- gen: 128 new rows 16..143 (t = t0+128+8 .. t0+263) ----
        int t0n = t0 + TT;
#pragma unroll
        for (int it = 0; it < 8; it++) {
            int rr = 16 + it * 16 + warp;        // 16..143
            int t  = t0n + rr - 8;
            int tr = (t > 2047) ? (4094 - t) : t;
            int m  = mbase + tr;
            float2 p = ms[m * 5 + head];
            uint32_t e = ((uint32_t)m << s2log) + sidx;
            uint32_t o0, o1;
            threefry2x32(key0, key1, 0u, e, o0, o1);
            ring[rr * SW + lane] = fmaf(p.y, bits_to_normal(o0 ^ o1), p.x);
        }
        __syncthreads();
    }
}

// ---------------- Phase 3b: head-0 noise kernel (SW=16, TT=256, 256 threads) ----------------
template<int SW, int TT>
__global__ __launch_bounds__(256) void noise_tile_kernel(
    float* __restrict__ out, int head, int S2,
    uint32_t key0, uint32_t key1)
{
    constexpr int W = TT + 16;
    __shared__ float vbuf[W * SW];

    int tid = threadIdx.x;
    int s0 = blockIdx.x * SW;
    int t0 = blockIdx.y * TT;
    int b  = blockIdx.z;

    float kv[17];
#pragma unroll
    for (int d = 0; d < 17; d++)
        kv[d] = g_gauss[(b * 5 + head) * 17 + d];

    const float2* ms = (const float2*)g_musig0;

    constexpr int GEN_IT = (W * SW + 255) / 256;
#pragma unroll
    for (int it = 0; it < GEN_IT; it++) {
        int j = tid + it * 256;
        if (W * SW % 256 != 0 && j >= W * SW) break;
        int tt = j / SW;
        int ss = j - tt * SW;
        int t = t0 - 8 + tt;
        int tr = (t < 0) ? -t : ((t > 2047) ? (4094 - t) : t);
        int m = b * 2048 + tr;
        float2 p = ms[m * 5 + head];
        uint32_t e = (uint32_t)m * (uint32_t)S2 + (uint32_t)(s0 + ss);
        uint32_t o0, o1;
        threefry2x32(key0, key1, 0u, e, o0, o1);
        vbuf[j] = fmaf(p.y, bits_to_normal(o0 ^ o1), p.x);
    }
    __syncthreads();

    int os  = tid & (SW - 1);
    int grp = tid / SW;
    int ot0 = grp * 16;

    float w[32];
#pragma unroll
    for (int j = 0; j < 32; j++)
        w[j] = vbuf[(ot0 + j) * SW + os];

    size_t ob = ((size_t)(b * 2048 + t0 + ot0)) * (size_t)S2 + (size_t)(s0 + os);
#pragma unroll
    for (int o = 0; o < 16; o++) {
        float a = 0.f;
#pragma unroll
        for (int d = 0; d < 17; d++)
            a = fmaf(kv[d], w[o + d], a);
        __stcs(out + ob + (size_t)o * S2, a);
    }
}

// ---------------- launch ----------------
extern "C" void kernel_launch(void* const* d_in, const int* in_sizes, int n_in,
                              void* d_out, int out_size)
{
    const float *x = 0, *w1 = 0, *b1 = 0, *w2 = 0, *b2 = 0, *ws = 0, *bs = 0;
    for (int i = 0; i < n_in; i++) {
        switch (in_sizes[i]) {
            case 16777216: x  = (const float*)d_in[i]; break;
            case 655360:   w1 = (const float*)d_in[i]; break;
            case 1280:     b1 = (const float*)d_in[i]; break;
            case 512:      w2 = (const float*)d_in[i]; break;
            case 256:      ws = (const float*)d_in[i]; break;
            case 2:        b2 = (const float*)d_in[i]; break;
            case 1:        bs = (const float*)d_in[i]; break;
        }
    }
    float* out = (float*)d_out;

    convert_x<<<16384, 256>>>(x);
    convert_w<<<2560, 256>>>(w1);

    dim3 grid(256, 10);
    gemm_mma_kernel<<<grid, 256>>>(b1, w2, ws);
    combine_kernel<<<640, 256>>>(b2);
    reduce_gauss_kernel<<<1, 128>>>(bs);

    // per-head output offsets
    size_t offs[5];
    size_t off = 0;
    for (int i = 0; i < 5; i++) {
        int S2 = (4 << i) * (4 << i);
        offs[i] = off;
        off += (size_t)16 * 2048 * (size_t)S2;
    }

    // launch largest head first
    for (int i = 4; i >= 1; i--) {
        int S2 = (4 << i) * (4 << i);
        int s2log = 4 + 2 * i;
        uint32_t f0, f1;
        threefry2x32(0u, 1u, 0u, (uint32_t)i, f0, f1);
        dim3 g(S2 / 32, 16);
        noise_ring_kernel<<<g, 512>>>(out + offs[i], i, S2, s2log, f0, f1);
    }
    {
        uint32_t f0, f1;
        threefry2x32(0u, 1u, 0u, 0u, f0, f1);
        dim3 g(1, 2048 / 256, 16);
        noise_tile_kernel<16, 256><<<g, 256>>>(out + offs[0], 0, 16, f0, f1);
    }
}

// round 7
// speedup vs baseline: 1.0558x; 1.0558x over previous
#include <cuda_runtime.h>
#include <cuda_bf16.h>
#include <cstdint>

// B=16, T=2048, C=512, H=256, NO=5, R=8

// ---------------- device scratch ----------------
__device__ float g_musig0[32768 * 5 * 2];
__device__ float g_musig1[32768 * 5 * 2];
__device__ float g_smpart[16 * 5 * 16 * 2];
__device__ float g_gauss[16 * 5 * 17];
__device__ __nv_bfloat16 g_xh[16777216];
__device__ __nv_bfloat16 g_xl[16777216];
__device__ __nv_bfloat16 g_wh[655360];   // transposed: [head][d][k]
__device__ __nv_bfloat16 g_wl[655360];

// ---------------- threefry2x32 (JAX-compatible) ----------------
__host__ __device__ __forceinline__ uint32_t rotl32(uint32_t x, uint32_t r) {
    return (x << r) | (x >> (32u - r));
}
__host__ __device__ __forceinline__ void threefry2x32(
    uint32_t k0, uint32_t k1, uint32_t x0, uint32_t x1,
    uint32_t& o0, uint32_t& o1)
{
    uint32_t k2 = k0 ^ k1 ^ 0x1BD11BDAu;
    x0 += k0; x1 += k1;
#define TF_R(r) { x0 += x1; x1 = rotl32(x1, r); x1 ^= x0; }
    TF_R(13) TF_R(15) TF_R(26) TF_R(6)   x0 += k1; x1 += k2 + 1u;
    TF_R(17) TF_R(29) TF_R(16) TF_R(24)  x0 += k2; x1 += k0 + 2u;
    TF_R(13) TF_R(15) TF_R(26) TF_R(6)   x0 += k0; x1 += k1 + 3u;
    TF_R(17) TF_R(29) TF_R(16) TF_R(24)  x0 += k1; x1 += k2 + 4u;
    TF_R(13) TF_R(15) TF_R(26) TF_R(6)   x0 += k2; x1 += k0 + 5u;
#undef TF_R
    o0 = x0; o1 = x1;
}

__device__ __forceinline__ float bits_to_normal(uint32_t bits) {
    float f = __uint_as_float((bits >> 9) | 0x3f800000u) - 1.0f;
    const float LO = -0.99999994f;
    float u = fmaf(f, 2.0f, LO);
    u = fmaxf(LO, u);
    return 1.41421356237f * erfinvf(u);
}

__device__ __forceinline__ float gelu_exact(float v) {
    return 0.5f * v * (1.0f + erff(v * 0.70710678118654752f));
}

// ---------------- PTX helpers ----------------
__device__ __forceinline__ void cp_async16(uint32_t dst, const void* src) {
    asm volatile("cp.async.cg.shared.global [%0], [%1], 16;\n" :: "r"(dst), "l"(src));
}
__device__ __forceinline__ void ldm_x4(uint32_t& r0, uint32_t& r1, uint32_t& r2, uint32_t& r3, uint32_t addr) {
    asm volatile("ldmatrix.sync.aligned.m8n8.x4.shared.b16 {%0,%1,%2,%3}, [%4];\n"
        : "=r"(r0), "=r"(r1), "=r"(r2), "=r"(r3) : "r"(addr));
}
__device__ __forceinline__ void mma16816(float* c, const uint32_t* a, uint32_t b0, uint32_t b1) {
    asm volatile(
        "mma.sync.aligned.m16n8k16.row.col.f32.bf16.bf16.f32 "
        "{%0,%1,%2,%3},{%4,%5,%6,%7},{%8,%9},{%0,%1,%2,%3};\n"
        : "+f"(c[0]), "+f"(c[1]), "+f"(c[2]), "+f"(c[3])
        : "r"(a[0]), "r"(a[1]), "r"(a[2]), "r"(a[3]), "r"(b0), "r"(b1));
}

// ---------------- Phase 0: precision-split conversions ----------------
__global__ __launch_bounds__(256) void convert_x(const float* __restrict__ x) {
    int i = (blockIdx.x * 256 + threadIdx.x) * 4;
    float4 v = *(const float4*)(x + i);
    __nv_bfloat16 h0 = __float2bfloat16_rn(v.x), h1 = __float2bfloat16_rn(v.y);
    __nv_bfloat16 h2 = __float2bfloat16_rn(v.z), h3 = __float2bfloat16_rn(v.w);
    __nv_bfloat16 l0 = __float2bfloat16_rn(v.x - __bfloat162float(h0));
    __nv_bfloat16 l1 = __float2bfloat16_rn(v.y - __bfloat162float(h1));
    __nv_bfloat16 l2 = __float2bfloat16_rn(v.z - __bfloat162float(h2));
    __nv_bfloat16 l3 = __float2bfloat16_rn(v.w - __bfloat162float(h3));
    *(__nv_bfloat162*)(g_xh + i)     = __nv_bfloat162(h0, h1);
    *(__nv_bfloat162*)(g_xh + i + 2) = __nv_bfloat162(h2, h3);
    *(__nv_bfloat162*)(g_xl + i)     = __nv_bfloat162(l0, l1);
    *(__nv_bfloat162*)(g_xl + i + 2) = __nv_bfloat162(l2, l3);
}

__global__ __launch_bounds__(256) void convert_w(const float* __restrict__ w1) {
    int idx = blockIdx.x * 256 + threadIdx.x;    // 655360 total
    if (idx >= 655360) return;
    int head = idx / (512 * 256);
    int r = idx % (512 * 256);
    int k = r / 256, d = r % 256;
    float v = w1[idx];
    __nv_bfloat16 h = __float2bfloat16_rn(v);
    __nv_bfloat16 l = __float2bfloat16_rn(v - __bfloat162float(h));
    int o = head * 131072 + d * 512 + k;
    g_wh[o] = h;
    g_wl[o] = l;
}

// ---------------- Phase 1: bf16 split tensor-core GEMM + fused epilogue ----------------
__global__ __launch_bounds__(256) void gemm_mma_kernel(
    const float* __restrict__ b1, const float* __restrict__ w2,
    const float* __restrict__ ws)
{
    __shared__ __nv_bfloat16 As[2][128 * 40];
    __shared__ __nv_bfloat16 Bs[2][128 * 40];
    __shared__ float cb1[128], cw20[128], cw21[128], cwsv[128];
    __shared__ float red[2][128][3];
    __shared__ float swred[4];

    int tid = threadIdx.x;
    int lane = tid & 31, warp = tid >> 5;
    int warpM = warp >> 1, warpN = warp & 1;
    int bx = blockIdx.x;
    int head = blockIdx.y >> 1;
    int dtile = blockIdx.y & 1;
    int d0 = dtile * 128;

    uint32_t AsBase = (uint32_t)__cvta_generic_to_shared(&As[0][0]);
    uint32_t BsBase = (uint32_t)__cvta_generic_to_shared(&Bs[0][0]);

    if (tid < 128) {
        int d = d0 + tid;
        cb1[tid]  = b1[head * 256 + d];
        cw20[tid] = w2[d * 2 + 0];
        cw21[tid] = w2[d * 2 + 1];
        cwsv[tid] = ws[d];
    }

    int crow = tid >> 2, cc8 = (tid & 3) * 8;

    auto issue = [&](int s, int buf) {
        int term = s >> 4;
        int k0 = (s & 15) * 32;
        const __nv_bfloat16* Asrc = (term == 2) ? g_xl : g_xh;
        const __nv_bfloat16* Bsrc = (term == 1) ? g_wl : g_wh;
#pragma unroll
        for (int it = 0; it < 2; it++) {
            int row = crow + it * 64;
            cp_async16(AsBase + buf * 10240u + (uint32_t)(row * 40 + cc8) * 2u,
                       Asrc + (size_t)(bx * 128 + row) * 512 + k0 + cc8);
            cp_async16(BsBase + buf * 10240u + (uint32_t)(row * 40 + cc8) * 2u,
                       Bsrc + (size_t)head * 131072 + (size_t)(d0 + row) * 512 + k0 + cc8);
        }
        asm volatile("cp.async.commit_group;\n");
    };

    float acc[2][8][4];
#pragma unroll
    for (int mt = 0; mt < 2; mt++)
#pragma unroll
        for (int nf = 0; nf < 8; nf++)
#pragma unroll
            for (int r = 0; r < 4; r++) acc[mt][nf][r] = 0.f;

    int lr = lane & 15, lc = (lane >> 4) * 8;

    issue(0, 0);
    __syncthreads();

    for (int s = 0; s < 48; s++) {
        int buf = s & 1;
        if (s < 47) issue(s + 1, buf ^ 1);
        if (s < 47) { asm volatile("cp.async.wait_group 1;\n"); }
        else        { asm volatile("cp.async.wait_group 0;\n"); }
        __syncthreads();

#pragma unroll
        for (int kstep = 0; kstep < 2; kstep++) {
            int k0 = kstep * 16;
            uint32_t a[2][4], bf[4][4];
#pragma unroll
            for (int mt = 0; mt < 2; mt++) {
                uint32_t addr = AsBase + buf * 10240u +
                    (uint32_t)((warpM * 32 + mt * 16 + lr) * 40 + k0 + lc) * 2u;
                ldm_x4(a[mt][0], a[mt][1], a[mt][2], a[mt][3], addr);
            }
#pragma unroll
            for (int g = 0; g < 4; g++) {
                uint32_t addr = BsBase + buf * 10240u +
                    (uint32_t)((warpN * 64 + g * 16 + lr) * 40 + k0 + lc) * 2u;
                ldm_x4(bf[g][0], bf[g][1], bf[g][2], bf[g][3], addr);
            }
#pragma unroll
            for (int mt = 0; mt < 2; mt++)
#pragma unroll
                for (int g = 0; g < 4; g++) {
                    mma16816(acc[mt][g * 2 + 0], a[mt], bf[g][0], bf[g][2]);
                    mma16816(acc[mt][g * 2 + 1], a[mt], bf[g][1], bf[g][3]);
                }
        }
        __syncthreads();
    }

#pragma unroll
    for (int mt = 0; mt < 2; mt++) {
#pragma unroll
        for (int r2 = 0; r2 < 2; r2++) {
            float pm = 0.f, ps = 0.f, pw = 0.f;
#pragma unroll
            for (int nf = 0; nf < 8; nf++) {
#pragma unroll
                for (int c01 = 0; c01 < 2; c01++) {
                    int col = warpN * 64 + nf * 8 + (lane & 3) * 2 + c01;
                    float h = gelu_exact(acc[mt][nf][r2 * 2 + c01] + cb1[col]);
                    pm = fmaf(h, cw20[col], pm);
                    ps = fmaf(h, cw21[col], ps);
                    pw = fmaf(h, cwsv[col], pw);
                }
            }
            pm += __shfl_xor_sync(0xffffffffu, pm, 1);
            pm += __shfl_xor_sync(0xffffffffu, pm, 2);
            ps += __shfl_xor_sync(0xffffffffu, ps, 1);
            ps += __shfl_xor_sync(0xffffffffu, ps, 2);
            pw += __shfl_xor_sync(0xffffffffu, pw, 1);
            pw += __shfl_xor_sync(0xffffffffu, pw, 2);
            if ((lane & 3) == 0) {
                int row = warpM * 32 + mt * 16 + (lane >> 2) + r2 * 8;
                red[warpN][row][0] = pm;
                red[warpN][row][1] = ps;
                red[warpN][row][2] = pw;
            }
        }
    }
    __syncthreads();

    if (tid < 128) {
        int row = tid;
        int m = bx * 128 + row;
        float mu  = red[0][row][0] + red[1][row][0];
        float sig = red[0][row][1] + red[1][row][1];
        float wv  = red[0][row][2] + red[1][row][2];
        float* dst = dtile ? g_musig1 : g_musig0;
        dst[((size_t)m * 5 + head) * 2 + 0] = mu;
        dst[((size_t)m * 5 + head) * 2 + 1] = sig;
#pragma unroll
        for (int off = 16; off >= 1; off >>= 1)
            wv += __shfl_xor_sync(0xffffffffu, wv, off);
        if ((tid & 31) == 0) swred[tid >> 5] = wv;
    }
    __syncthreads();
    if (tid == 0) {
        float s = swred[0] + swred[1] + swred[2] + swred[3];
        int b = bx >> 4, mblk = bx & 15;
        g_smpart[((b * 5 + head) * 16 + mblk) * 2 + dtile] = s;
    }
}

// ---------------- Phase 2a: combine d-tile partials + b2 ----------------
__global__ void combine_kernel(const float* __restrict__ b2) {
    int i = blockIdx.x * 256 + threadIdx.x;
    if (i >= 32768 * 5) return;
    float2* p0 = (float2*)g_musig0;
    float2* p1 = (float2*)g_musig1;
    float2 a = p0[i], c = p1[i];
    p0[i] = make_float2(a.x + c.x + b2[0], a.y + c.y + b2[1]);
}

// ---------------- Phase 2b: smooths -> normalized gaussian kernels ----------------
__global__ void reduce_gauss_kernel(const float* __restrict__ bs) {
    int id = threadIdx.x;
    if (id >= 80) return;
    float s = 0.f;
#pragma unroll
    for (int j = 0; j < 32; j++) s += g_smpart[id * 32 + j];
    float sig = s * (1.0f / 2048.0f) + bs[0];
    float denom = sig * sig + 1e-6f;
    float kv[17];
    float ksum = 0.f;
#pragma unroll
    for (int d = 0; d < 17; d++) {
        float t = (float)(d - 8);
        kv[d] = expf(-0.5f * t * t / denom);
        ksum += kv[d];
    }
    float inv = 1.0f / ksum;
#pragma unroll
    for (int d = 0; d < 17; d++) g_gauss[id * 17 + d] = kv[d] * inv;
}

// ---------------- Phase 3a: big-head noise kernel (SW=32, TT=256, 512 thr, 2 blk/SM) ----------------
// Window (TT+16)x32 in smem (halo 6.25%). Conv in two passes of 8 outputs with a 24-float
// register window to keep regs <= 64 so TWO blocks co-reside per SM: one block's ALU-heavy
// gen phase overlaps the other's FMA-heavy conv phase.
__global__ __launch_bounds__(512, 2) void noise_tile2_kernel(
    float* __restrict__ out, int head, int S2,
    uint32_t key0, uint32_t key1)
{
    constexpr int SW = 32;
    constexpr int TT = 256;
    constexpr int W = TT + 16;            // 272
    __shared__ float vbuf[W * SW];        // 34816 B

    int tid = threadIdx.x;
    int s0 = blockIdx.x * SW;
    int t0 = blockIdx.y * TT;
    int b  = blockIdx.z;

    float kv[17];
#pragma unroll
    for (int d = 0; d < 17; d++)
        kv[d] = g_gauss[(b * 5 + head) * 17 + d];

    const float2* ms = (const float2*)g_musig0;

    // ---- gen: 272 rows x 32 cols, 16 rows per iteration x 17 iterations ----
    int ss = tid & 31;
    int r0 = tid >> 5;
#pragma unroll
    for (int it = 0; it < W / 16; it++) {
        int tt = it * 16 + r0;
        int t = t0 - 8 + tt;
        int tr = (t < 0) ? -t : ((t > 2047) ? (4094 - t) : t);
        int m = b * 2048 + tr;
        float2 p = ms[m * 5 + head];      // warp-uniform broadcast
        uint32_t e = (uint32_t)m * (uint32_t)S2 + (uint32_t)(s0 + ss);
        uint32_t o0, o1;
        threefry2x32(key0, key1, 0u, e, o0, o1);
        vbuf[tt * SW + ss] = fmaf(p.y, bits_to_normal(o0 ^ o1), p.x);
    }
    __syncthreads();

    // ---- conv: 512 threads; warp owns 16 out rows, two passes of 8 (w[24] window) ----
    int os  = tid & 31;
    int grp = tid >> 5;                   // 0..15
    int ot0 = grp * 16;

    size_t obBase = ((size_t)(b * 2048 + t0 + ot0)) * (size_t)S2 + (size_t)(s0 + os);
#pragma unroll
    for (int pass = 0; pass < 2; pass++) {
        int base = ot0 + pass * 8;
        float w[24];
#pragma unroll
        for (int j = 0; j < 24; j++)
            w[j] = vbuf[(base + j) * SW + os];

        size_t ob = obBase + (size_t)(pass * 8) * S2;
#pragma unroll
        for (int o = 0; o < 8; o++) {
            float a = 0.f;
#pragma unroll
            for (int d = 0; d < 17; d++)
                a = fmaf(kv[d], w[o + d], a);
            __stcs(out + ob + (size_t)o * S2, a);
        }
    }
}

// ---------------- Phase 3b: head-0 noise kernel (SW=16, TT=256, 256 threads) ----------------
template<int SW, int TT>
__global__ __launch_bounds__(256) void noise_tile_kernel(
    float* __restrict__ out, int head, int S2,
    uint32_t key0, uint32_t key1)
{
    constexpr int W = TT + 16;
    __shared__ float vbuf[W * SW];

    int tid = threadIdx.x;
    int s0 = blockIdx.x * SW;
    int t0 = blockIdx.y * TT;
    int b  = blockIdx.z;

    float kv[17];
#pragma unroll
    for (int d = 0; d < 17; d++)
        kv[d] = g_gauss[(b * 5 + head) * 17 + d];

    const float2* ms = (const float2*)g_musig0;

    constexpr int GEN_IT = (W * SW + 255) / 256;
#pragma unroll
    for (int it = 0; it < GEN_IT; it++) {
        int j = tid + it * 256;
        if (W * SW % 256 != 0 && j >= W * SW) break;
        int tt = j / SW;
        int ss = j - tt * SW;
        int t = t0 - 8 + tt;
        int tr = (t < 0) ? -t : ((t > 2047) ? (4094 - t) : t);
        int m = b * 2048 + tr;
        float2 p = ms[m * 5 + head];
        uint32_t e = (uint32_t)m * (uint32_t)S2 + (uint32_t)(s0 + ss);
        uint32_t o0, o1;
        threefry2x32(key0, key1, 0u, e, o0, o1);
        vbuf[j] = fmaf(p.y, bits_to_normal(o0 ^ o1), p.x);
    }
    __syncthreads();

    int os  = tid & (SW - 1);
    int grp = tid / SW;
    int ot0 = grp * 16;

    float w[32];
#pragma unroll
    for (int j = 0; j < 32; j++)
        w[j] = vbuf[(ot0 + j) * SW + os];

    size_t ob = ((size_t)(b * 2048 + t0 + ot0)) * (size_t)S2 + (size_t)(s0 + os);
#pragma unroll
    for (int o = 0; o < 16; o++) {
        float a = 0.f;
#pragma unroll
        for (int d = 0; d < 17; d++)
            a = fmaf(kv[d], w[o + d], a);
        __stcs(out + ob + (size_t)o * S2, a);
    }
}

// ---------------- launch ----------------
extern "C" void kernel_launch(void* const* d_in, const int* in_sizes, int n_in,
                              void* d_out, int out_size)
{
    const float *x = 0, *w1 = 0, *b1 = 0, *w2 = 0, *b2 = 0, *ws = 0, *bs = 0;
    for (int i = 0; i < n_in; i++) {
        switch (in_sizes[i]) {
            case 16777216: x  = (const float*)d_in[i]; break;
            case 655360:   w1 = (const float*)d_in[i]; break;
            case 1280:     b1 = (const float*)d_in[i]; break;
            case 512:      w2 = (const float*)d_in[i]; break;
            case 256:      ws = (const float*)d_in[i]; break;
            case 2:        b2 = (const float*)d_in[i]; break;
            case 1:        bs = (const float*)d_in[i]; break;
        }
    }
    float* out = (float*)d_out;

    convert_x<<<16384, 256>>>(x);
    convert_w<<<2560, 256>>>(w1);

    dim3 grid(256, 10);
    gemm_mma_kernel<<<grid, 256>>>(b1, w2, ws);
    combine_kernel<<<640, 256>>>(b2);
    reduce_gauss_kernel<<<1, 128>>>(bs);

    // per-head output offsets
    size_t offs[5];
    size_t off = 0;
    for (int i = 0; i < 5; i++) {
        int S2 = (4 << i) * (4 << i);
        offs[i] = off;
        off += (size_t)16 * 2048 * (size_t)S2;
    }

    // launch largest head first
    for (int i = 4; i >= 1; i--) {
        int S2 = (4 << i) * (4 << i);
        uint32_t f0, f1;
        threefry2x32(0u, 1u, 0u, (uint32_t)i, f0, f1);
        dim3 g(S2 / 32, 2048 / 256, 16);
        noise_tile2_kernel<<<g, 512>>>(out + offs[i], i, S2, f0, f1);
    }
    {
        uint32_t f0, f1;
        threefry2x32(0u, 1u, 0u, 0u, f0, f1);
        dim3 g(1, 2048 / 256, 16);
        noise_tile_kernel<16, 256><<<g, 256>>>(out + offs[0], 0, 16, f0, f1);
    }
}

// round 10
// speedup vs baseline: 1.0991x; 1.0410x over previous
#include <cuda_runtime.h>
#include <cuda_bf16.h>
#include <cstdint>

// B=16, T=2048, C=512, H=256, NO=5, R=8

// ---------------- device scratch ----------------
__device__ float g_musig0[32768 * 5 * 2];
__device__ float g_musig1[32768 * 5 * 2];
__device__ float g_smpart[16 * 5 * 16 * 2];
__device__ float g_gauss[16 * 5 * 17];
__device__ __nv_bfloat16 g_xh[16777216];
__device__ __nv_bfloat16 g_xl[16777216];
__device__ __nv_bfloat16 g_wh[655360];   // transposed: [head][d][k]
__device__ __nv_bfloat16 g_wl[655360];

// ---------------- threefry2x32 (JAX-compatible) ----------------
__host__ __device__ __forceinline__ uint32_t rotl32(uint32_t x, uint32_t r) {
    return (x << r) | (x >> (32u - r));
}
__host__ __device__ __forceinline__ void threefry2x32(
    uint32_t k0, uint32_t k1, uint32_t x0, uint32_t x1,
    uint32_t& o0, uint32_t& o1)
{
    uint32_t k2 = k0 ^ k1 ^ 0x1BD11BDAu;
    x0 += k0; x1 += k1;
#define TF_R(r) { x0 += x1; x1 = rotl32(x1, r); x1 ^= x0; }
    TF_R(13) TF_R(15) TF_R(26) TF_R(6)   x0 += k1; x1 += k2 + 1u;
    TF_R(17) TF_R(29) TF_R(16) TF_R(24)  x0 += k2; x1 += k0 + 2u;
    TF_R(13) TF_R(15) TF_R(26) TF_R(6)   x0 += k0; x1 += k1 + 3u;
    TF_R(17) TF_R(29) TF_R(16) TF_R(24)  x0 += k1; x1 += k2 + 4u;
    TF_R(13) TF_R(15) TF_R(26) TF_R(6)   x0 += k2; x1 += k0 + 5u;
#undef TF_R
    o0 = x0; o1 = x1;
}

__device__ __forceinline__ float bits_to_normal(uint32_t bits) {
    float f = __uint_as_float((bits >> 9) | 0x3f800000u) - 1.0f;
    const float LO = -0.99999994f;
    float u = fmaf(f, 2.0f, LO);
    u = fmaxf(LO, u);
    return 1.41421356237f * erfinvf(u);
}

__device__ __forceinline__ float gelu_exact(float v) {
    return 0.5f * v * (1.0f + erff(v * 0.70710678118654752f));
}

// ---------------- PTX helpers ----------------
__device__ __forceinline__ void cp_async16(uint32_t dst, const void* src) {
    asm volatile("cp.async.cg.shared.global [%0], [%1], 16;\n" :: "r"(dst), "l"(src));
}
__device__ __forceinline__ void ldm_x4(uint32_t& r0, uint32_t& r1, uint32_t& r2, uint32_t& r3, uint32_t addr) {
    asm volatile("ldmatrix.sync.aligned.m8n8.x4.shared.b16 {%0,%1,%2,%3}, [%4];\n"
        : "=r"(r0), "=r"(r1), "=r"(r2), "=r"(r3) : "r"(addr));
}
__device__ __forceinline__ void mma16816(float* c, const uint32_t* a, uint32_t b0, uint32_t b1) {
    asm volatile(
        "mma.sync.aligned.m16n8k16.row.col.f32.bf16.bf16.f32 "
        "{%0,%1,%2,%3},{%4,%5,%6,%7},{%8,%9},{%0,%1,%2,%3};\n"
        : "+f"(c[0]), "+f"(c[1]), "+f"(c[2]), "+f"(c[3])
        : "r"(a[0]), "r"(a[1]), "r"(a[2]), "r"(a[3]), "r"(b0), "r"(b1));
}
#define PACK_F32X2(out, lo, hi) \
    asm("mov.b64 %0, {%1, %2};" : "=l"(out) : "f"(lo), "f"(hi))
#define UNPACK_F32X2(lo, hi, in) \
    asm("mov.b64 {%0, %1}, %2;" : "=f"(lo), "=f"(hi) : "l"(in))
#define FMA_F32X2(d, a, b, c) \
    asm("fma.rn.f32x2 %0, %1, %2, %3;" : "=l"(d) : "l"(a), "l"(b), "l"(c))

// ---------------- Phase 0: precision-split conversions ----------------
__global__ __launch_bounds__(256) void convert_x(const float* __restrict__ x) {
    int i = (blockIdx.x * 256 + threadIdx.x) * 4;
    float4 v = *(const float4*)(x + i);
    __nv_bfloat16 h0 = __float2bfloat16_rn(v.x), h1 = __float2bfloat16_rn(v.y);
    __nv_bfloat16 h2 = __float2bfloat16_rn(v.z), h3 = __float2bfloat16_rn(v.w);
    __nv_bfloat16 l0 = __float2bfloat16_rn(v.x - __bfloat162float(h0));
    __nv_bfloat16 l1 = __float2bfloat16_rn(v.y - __bfloat162float(h1));
    __nv_bfloat16 l2 = __float2bfloat16_rn(v.z - __bfloat162float(h2));
    __nv_bfloat16 l3 = __float2bfloat16_rn(v.w - __bfloat162float(h3));
    *(__nv_bfloat162*)(g_xh + i)     = __nv_bfloat162(h0, h1);
    *(__nv_bfloat162*)(g_xh + i + 2) = __nv_bfloat162(h2, h3);
    *(__nv_bfloat162*)(g_xl + i)     = __nv_bfloat162(l0, l1);
    *(__nv_bfloat162*)(g_xl + i + 2) = __nv_bfloat162(l2, l3);
}

__global__ __launch_bounds__(256) void convert_w(const float* __restrict__ w1) {
    int idx = blockIdx.x * 256 + threadIdx.x;    // 655360 total
    if (idx >= 655360) return;
    int head = idx / (512 * 256);
    int r = idx % (512 * 256);
    int k = r / 256, d = r % 256;
    float v = w1[idx];
    __nv_bfloat16 h = __float2bfloat16_rn(v);
    __nv_bfloat16 l = __float2bfloat16_rn(v - __bfloat162float(h));
    int o = head * 131072 + d * 512 + k;
    g_wh[o] = h;
    g_wl[o] = l;
}

// ---------------- Phase 1: bf16 split tensor-core GEMM + fused epilogue ----------------
// Logical K' = 1536: 48 stages of BK=32; term = stage/16 in {(hi,hi),(hi,lo),(lo,hi)}.
__global__ __launch_bounds__(256) void gemm_mma_kernel(
    const float* __restrict__ b1, const float* __restrict__ w2,
    const float* __restrict__ ws)
{
    __shared__ __nv_bfloat16 As[2][128 * 40];
    __shared__ __nv_bfloat16 Bs[2][128 * 40];
    __shared__ float cb1[128], cw20[128], cw21[128], cwsv[128];
    __shared__ float red[2][128][3];
    __shared__ float swred[4];

    int tid = threadIdx.x;
    int lane = tid & 31, warp = tid >> 5;
    int warpM = warp >> 1, warpN = warp & 1;
    int bx = blockIdx.x;
    int head = blockIdx.y >> 1;
    int dtile = blockIdx.y & 1;
    int d0 = dtile * 128;

    uint32_t AsBase = (uint32_t)__cvta_generic_to_shared(&As[0][0]);
    uint32_t BsBase = (uint32_t)__cvta_generic_to_shared(&Bs[0][0]);

    if (tid < 128) {
        int d = d0 + tid;
        cb1[tid]  = b1[head * 256 + d];
        cw20[tid] = w2[d * 2 + 0];
        cw21[tid] = w2[d * 2 + 1];
        cwsv[tid] = ws[d];
    }

    int crow = tid >> 2, cc8 = (tid & 3) * 8;

    auto issue = [&](int s, int buf) {
        int term = s >> 4;
        int k0 = (s & 15) * 32;
        const __nv_bfloat16* Asrc = (term == 2) ? g_xl : g_xh;
        const __nv_bfloat16* Bsrc = (term == 1) ? g_wl : g_wh;
#pragma unroll
        for (int it = 0; it < 2; it++) {
            int row = crow + it * 64;
            cp_async16(AsBase + buf * 10240u + (uint32_t)(row * 40 + cc8) * 2u,
                       Asrc + (size_t)(bx * 128 + row) * 512 + k0 + cc8);
            cp_async16(BsBase + buf * 10240u + (uint32_t)(row * 40 + cc8) * 2u,
                       Bsrc + (size_t)head * 131072 + (size_t)(d0 + row) * 512 + k0 + cc8);
        }
        asm volatile("cp.async.commit_group;\n");
    };

    float acc[2][8][4];
#pragma unroll
    for (int mt = 0; mt < 2; mt++)
#pragma unroll
        for (int nf = 0; nf < 8; nf++)
#pragma unroll
            for (int r = 0; r < 4; r++) acc[mt][nf][r] = 0.f;

    int lr = lane & 15, lc = (lane >> 4) * 8;

    issue(0, 0);
    __syncthreads();

    for (int s = 0; s < 48; s++) {
        int buf = s & 1;
        if (s < 47) issue(s + 1, buf ^ 1);
        if (s < 47) { asm volatile("cp.async.wait_group 1;\n"); }
        else        { asm volatile("cp.async.wait_group 0;\n"); }
        __syncthreads();

#pragma unroll
        for (int kstep = 0; kstep < 2; kstep++) {
            int k0 = kstep * 16;
            uint32_t a[2][4], bf[4][4];
#pragma unroll
            for (int mt = 0; mt < 2; mt++) {
                uint32_t addr = AsBase + buf * 10240u +
                    (uint32_t)((warpM * 32 + mt * 16 + lr) * 40 + k0 + lc) * 2u;
                ldm_x4(a[mt][0], a[mt][1], a[mt][2], a[mt][3], addr);
            }
#pragma unroll
            for (int g = 0; g < 4; g++) {
                uint32_t addr = BsBase + buf * 10240u +
                    (uint32_t)((warpN * 64 + g * 16 + lr) * 40 + k0 + lc) * 2u;
                ldm_x4(bf[g][0], bf[g][1], bf[g][2], bf[g][3], addr);
            }
#pragma unroll
            for (int mt = 0; mt < 2; mt++)
#pragma unroll
                for (int g = 0; g < 4; g++) {
                    mma16816(acc[mt][g * 2 + 0], a[mt], bf[g][0], bf[g][2]);
                    mma16816(acc[mt][g * 2 + 1], a[mt], bf[g][1], bf[g][3]);
                }
        }
        __syncthreads();
    }

#pragma unroll
    for (int mt = 0; mt < 2; mt++) {
#pragma unroll
        for (int r2 = 0; r2 < 2; r2++) {
            float pm = 0.f, ps = 0.f, pw = 0.f;
#pragma unroll
            for (int nf = 0; nf < 8; nf++) {
#pragma unroll
                for (int c01 = 0; c01 < 2; c01++) {
                    int col = warpN * 64 + nf * 8 + (lane & 3) * 2 + c01;
                    float h = gelu_exact(acc[mt][nf][r2 * 2 + c01] + cb1[col]);
                    pm = fmaf(h, cw20[col], pm);
                    ps = fmaf(h, cw21[col], ps);
                    pw = fmaf(h, cwsv[col], pw);
                }
            }
            pm += __shfl_xor_sync(0xffffffffu, pm, 1);
            pm += __shfl_xor_sync(0xffffffffu, pm, 2);
            ps += __shfl_xor_sync(0xffffffffu, ps, 1);
            ps += __shfl_xor_sync(0xffffffffu, ps, 2);
            pw += __shfl_xor_sync(0xffffffffu, pw, 1);
            pw += __shfl_xor_sync(0xffffffffu, pw, 2);
            if ((lane & 3) == 0) {
                int row = warpM * 32 + mt * 16 + (lane >> 2) + r2 * 8;
                red[warpN][row][0] = pm;
                red[warpN][row][1] = ps;
                red[warpN][row][2] = pw;
            }
        }
    }
    __syncthreads();

    if (tid < 128) {
        int row = tid;
        int m = bx * 128 + row;
        float mu  = red[0][row][0] + red[1][row][0];
        float sig = red[0][row][1] + red[1][row][1];
        float wv  = red[0][row][2] + red[1][row][2];
        float* dst = dtile ? g_musig1 : g_musig0;
        dst[((size_t)m * 5 + head) * 2 + 0] = mu;
        dst[((size_t)m * 5 + head) * 2 + 1] = sig;
#pragma unroll
        for (int off = 16; off >= 1; off >>= 1)
            wv += __shfl_xor_sync(0xffffffffu, wv, off);
        if ((tid & 31) == 0) swred[tid >> 5] = wv;
    }
    __syncthreads();
    if (tid == 0) {
        float s = swred[0] + swred[1] + swred[2] + swred[3];
        int b = bx >> 4, mblk = bx & 15;
        g_smpart[((b * 5 + head) * 16 + mblk) * 2 + dtile] = s;
    }
}

// ---------------- Phase 2a: combine d-tile partials + b2 ----------------
__global__ void combine_kernel(const float* __restrict__ b2) {
    int i = blockIdx.x * 256 + threadIdx.x;
    if (i >= 32768 * 5) return;
    float2* p0 = (float2*)g_musig0;
    float2* p1 = (float2*)g_musig1;
    float2 a = p0[i], c = p1[i];
    p0[i] = make_float2(a.x + c.x + b2[0], a.y + c.y + b2[1]);
}

// ---------------- Phase 2b: smooths -> normalized gaussian kernels ----------------
__global__ void reduce_gauss_kernel(const float* __restrict__ bs) {
    int id = threadIdx.x;
    if (id >= 80) return;
    float s = 0.f;
#pragma unroll
    for (int j = 0; j < 32; j++) s += g_smpart[id * 32 + j];
    float sig = s * (1.0f / 2048.0f) + bs[0];
    float denom = sig * sig + 1e-6f;
    float kv[17];
    float ksum = 0.f;
#pragma unroll
    for (int d = 0; d < 17; d++) {
        float t = (float)(d - 8);
        kv[d] = expf(-0.5f * t * t / denom);
        ksum += kv[d];
    }
    float inv = 1.0f / ksum;
#pragma unroll
    for (int d = 0; d < 17; d++) g_gauss[id * 17 + d] = kv[d] * inv;
}

// ---------------- Phase 3a: big-head noise kernel (SW=32, TT=256, 512 threads) ----------------
// R5 structure. Gen phase: branch-free interior fast path with incremental counters
// (6/8 of blocks); conv uses packed f32x2 FMA pairing outputs o and o+8.
__global__ __launch_bounds__(512) void noise_tile2_kernel(
    float* __restrict__ out, int head, int S2,
    uint32_t key0, uint32_t key1)
{
    constexpr int SW = 32;
    constexpr int TT = 256;
    constexpr int W = TT + 16;            // 272
    __shared__ float vbuf[W * SW];        // 34816 B

    int tid = threadIdx.x;
    int s0 = blockIdx.x * SW;
    int t0 = blockIdx.y * TT;
    int b  = blockIdx.z;

    float kv[17];
#pragma unroll
    for (int d = 0; d < 17; d++)
        kv[d] = g_gauss[(b * 5 + head) * 17 + d];

    const float2* ms = (const float2*)g_musig0;

    int ss = tid & 31;
    int r0 = tid >> 5;

    if (blockIdx.y == 0 || blockIdx.y == 7) {
        // ---- edge path: reflect handling ----
#pragma unroll
        for (int it = 0; it < W / 16; it++) {
            int tt = it * 16 + r0;
            int t = t0 - 8 + tt;
            int tr = (t < 0) ? -t : ((t > 2047) ? (4094 - t) : t);
            int m = b * 2048 + tr;
            float2 p = ms[m * 5 + head];
            uint32_t e = (uint32_t)m * (uint32_t)S2 + (uint32_t)(s0 + ss);
            uint32_t o0, o1;
            threefry2x32(key0, key1, 0u, e, o0, o1);
            vbuf[tt * SW + ss] = fmaf(p.y, bits_to_normal(o0 ^ o1), p.x);
        }
    } else {
        // ---- interior fast path: linear counters, no reflect ----
        int m0 = b * 2048 + t0 - 8 + r0;
        uint32_t e = (uint32_t)m0 * (uint32_t)S2 + (uint32_t)(s0 + ss);
        uint32_t eStep = (uint32_t)(16 * S2);
        const float2* pp = ms + m0 * 5 + head;
        float* vb = vbuf + r0 * SW + ss;
#pragma unroll
        for (int it = 0; it < W / 16; it++) {
            float2 p = *pp;
            uint32_t o0, o1;
            threefry2x32(key0, key1, 0u, e, o0, o1);
            *vb = fmaf(p.y, bits_to_normal(o0 ^ o1), p.x);
            e += eStep;
            pp += 80;
            vb += 16 * SW;
        }
    }
    __syncthreads();

    // ---- conv: 512 threads, each 16 outputs (paired o / o+8 via f32x2) ----
    int os  = tid & 31;
    int grp = tid >> 5;                   // 0..15
    int ot0 = grp * 16;

    float w[32];
#pragma unroll
    for (int j = 0; j < 32; j++)
        w[j] = vbuf[(ot0 + j) * SW + os];

    unsigned long long kk[17];
#pragma unroll
    for (int d = 0; d < 17; d++)
        PACK_F32X2(kk[d], kv[d], kv[d]);

    unsigned long long pw[24];
#pragma unroll
    for (int j = 0; j < 24; j++)
        PACK_F32X2(pw[j], w[j], w[j + 8]);

    size_t ob = ((size_t)(b * 2048 + t0 + ot0)) * (size_t)S2 + (size_t)(s0 + os);
#pragma unroll
    for (int o = 0; o < 8; o++) {
        unsigned long long acc;
        PACK_F32X2(acc, 0.0f, 0.0f);
#pragma unroll
        for (int d = 0; d < 17; d++)
            FMA_F32X2(acc, kk[d], pw[o + d], acc);
        float lo, hi;
        UNPACK_F32X2(lo, hi, acc);
        __stcs(out + ob + (size_t)o * S2, lo);
        __stcs(out + ob + (size_t)(o + 8) * S2, hi);
    }
}

// ---------------- Phase 3b: head-0 noise kernel (SW=16, TT=256, 256 threads) ----------------
template<int SW, int TT>
__global__ __launch_bounds__(256) void noise_tile_kernel(
    float* __restrict__ out, int head, int S2,
    uint32_t key0, uint32_t key1)
{
    constexpr int W = TT + 16;
    __shared__ float vbuf[W * SW];

    int tid = threadIdx.x;
    int s0 = blockIdx.x * SW;
    int t0 = blockIdx.y * TT;
    int b  = blockIdx.z;

    float kv[17];
#pragma unroll
    for (int d = 0; d < 17; d++)
        kv[d] = g_gauss[(b * 5 + head) * 17 + d];

    const float2* ms = (const float2*)g_musig0;

    constexpr int GEN_IT = (W * SW + 255) / 256;
#pragma unroll
    for (int it = 0; it < GEN_IT; it++) {
        int j = tid + it * 256;
        if (W * SW % 256 != 0 && j >= W * SW) break;
        int tt = j / SW;
        int ss = j - tt * SW;
        int t = t0 - 8 + tt;
        int tr = (t < 0) ? -t : ((t > 2047) ? (4094 - t) : t);
        int m = b * 2048 + tr;
        float2 p = ms[m * 5 + head];
        uint32_t e = (uint32_t)m * (uint32_t)S2 + (uint32_t)(s0 + ss);
        uint32_t o0, o1;
        threefry2x32(key0, key1, 0u, e, o0, o1);
        vbuf[j] = fmaf(p.y, bits_to_normal(o0 ^ o1), p.x);
    }
    __syncthreads();

    int os  = tid & (SW - 1);
    int grp = tid / SW;
    int ot0 = grp * 16;

    float w[32];
#pragma unroll
    for (int j = 0; j < 32; j++)
        w[j] = vbuf[(ot0 + j) * SW + os];

    size_t ob = ((size_t)(b * 2048 + t0 + ot0)) * (size_t)S2 + (size_t)(s0 + os);
#pragma unroll
    for (int o = 0; o < 16; o++) {
        float a = 0.f;
#pragma unroll
        for (int d = 0; d < 17; d++)
            a = fmaf(kv[d], w[o + d], a);
        __stcs(out + ob + (size_t)o * S2, a);
    }
}

// ---------------- launch ----------------
extern "C" void kernel_launch(void* const* d_in, const int* in_sizes, int n_in,
                              void* d_out, int out_size)
{
    const float *x = 0, *w1 = 0, *b1 = 0, *w2 = 0, *b2 = 0, *ws = 0, *bs = 0;
    for (int i = 0; i < n_in; i++) {
        switch (in_sizes[i]) {
            case 16777216: x  = (const float*)d_in[i]; break;
            case 655360:   w1 = (const float*)d_in[i]; break;
            case 1280:     b1 = (const float*)d_in[i]; break;
            case 512:      w2 = (const float*)d_in[i]; break;
            case 256:      ws = (const float*)d_in[i]; break;
            case 2:        b2 = (const float*)d_in[i]; break;
            case 1:        bs = (const float*)d_in[i]; break;
        }
    }
    float* out = (float*)d_out;

    convert_x<<<16384, 256>>>(x);
    convert_w<<<2560, 256>>>(w1);

    dim3 grid(256, 10);
    gemm_mma_kernel<<<grid, 256>>>(b1, w2, ws);
    combine_kernel<<<640, 256>>>(b2);
    reduce_gauss_kernel<<<1, 128>>>(bs);

    // per-head output offsets
    size_t offs[5];
    size_t off = 0;
    for (int i = 0; i < 5; i++) {
        int S2 = (4 << i) * (4 << i);
        offs[i] = off;
        off += (size_t)16 * 2048 * (size_t)S2;
    }

    // launch largest head first
    for (int i = 4; i >= 1; i--) {
        int S2 = (4 << i) * (4 << i);
        uint32_t f0, f1;
        threefry2x32(0u, 1u, 0u, (uint32_t)i, f0, f1);
        dim3 g(S2 / 32, 2048 / 256, 16);
        noise_tile2_kernel<<<g, 512>>>(out + offs[i], i, S2, f0, f1);
    }
    {
        uint32_t f0, f1;
        threefry2x32(0u, 1u, 0u, 0u, f0, f1);
        dim3 g(1, 2048 / 256, 16);
        noise_tile_kernel<16, 256><<<g, 256>>>(out + offs[0], 0, 16, f0, f1);
    }
}